// round 9
// baseline (speedup 1.0000x reference)
#include <cuda_runtime.h>
#include <cuda_bf16.h>
#include <cstdint>

// out[b,h,o] = sum_d gathered[b,h,d] * W[h,o,d] + bias[h,o]
// gathered[b,h, 64*k + w] = x[b, mask[h,k], w]
// x:(512,128,64) f32, mask:(256,4) i32 (declared i64; JAX x64-off),
// W:(256,64,256) f32, b:(256,64) f32, out:(512,256,64) f32.
//
// Fused: stage f32 -> bf16 hi/lo in smem (XOR-swizzled), 3-pass
// mma.sync m16n8k16 (D = Ahi*Whi + Alo*Whi + Ahi*Wlo).
// CTA tile m64 x n64, 4 warps of m32 x n32, reg-capped for 4 CTAs/SM.

namespace asl {

constexpr int B_SZ = 512, H_IN = 128, W_IN = 64, H_OUT = 256, W_OUT = 64;
constexpr int KSEL = 4, D = 256;
constexpr int BM = 64;           // batch rows per CTA
constexpr int THREADS = 128;     // 4 warps, warp tile m32 x n32

__device__ __forceinline__ bool mask_is_i64(const int* m32) {
    int acc = 0;
#pragma unroll
    for (int i = 0; i < 16; ++i) acc |= m32[2 * i + 1];
    return acc == 0;
}
__device__ __forceinline__ int mask_val(const int* m32, bool is64, int idx) {
    int v = is64 ? m32[2 * idx] : m32[idx];
    return min(max(v, 0), H_IN - 1);
}

__device__ __forceinline__ void mma16816(float* c, const uint32_t* a, const uint32_t* b) {
    asm volatile(
        "mma.sync.aligned.m16n8k16.row.col.f32.bf16.bf16.f32 "
        "{%0,%1,%2,%3}, {%4,%5,%6,%7}, {%8,%9}, {%0,%1,%2,%3};"
        : "+f"(c[0]), "+f"(c[1]), "+f"(c[2]), "+f"(c[3])
        : "r"(a[0]), "r"(a[1]), "r"(a[2]), "r"(a[3]), "r"(b[0]), "r"(b[1]));
}

__device__ __forceinline__ void ldsm4(uint32_t* r, uint32_t saddr) {
    asm volatile("ldmatrix.sync.aligned.m8n8.x4.shared.b16 {%0,%1,%2,%3}, [%4];"
                 : "=r"(r[0]), "=r"(r[1]), "=r"(r[2]), "=r"(r[3]) : "r"(saddr));
}

__device__ __forceinline__ uint32_t smem_u32(const void* p) {
    uint32_t a;
    asm("{ .reg .u64 t; cvta.to.shared.u64 t, %1; cvt.u32.u64 %0, t; }" : "=r"(a) : "l"(p));
    return a;
}

// 8 f32 -> 4x hi-pairs + 4x lo-pairs (pair-packed bf16).
__device__ __forceinline__ void cvt8(float4 v0, float4 v1, uint4& hi, uint4& lo) {
    auto one = [](float p, float q, uint32_t& h, uint32_t& l) {
        __nv_bfloat162 hb = __floats2bfloat162_rn(p, q);
        float hp = __bfloat162float(hb.x), hq = __bfloat162float(hb.y);
        __nv_bfloat162 lb = __floats2bfloat162_rn(p - hp, q - hq);
        h = *reinterpret_cast<uint32_t*>(&hb);
        l = *reinterpret_cast<uint32_t*>(&lb);
    };
    one(v0.x, v0.y, hi.x, lo.x);
    one(v0.z, v0.w, hi.y, lo.y);
    one(v1.x, v1.y, hi.z, lo.z);
    one(v1.z, v1.w, hi.w, lo.w);
}

__global__ __launch_bounds__(THREADS, 4)
void fused_kernel(const float* __restrict__ x,
                  const int* __restrict__ mask32,
                  const float* __restrict__ W,
                  const float* __restrict__ bias,
                  float* __restrict__ out) {
    // Rows of 64 bf16 (128B = 8 chunks of 16B), chunks XOR-swizzled: phys = c ^ (r&7).
    __shared__ alignas(16) uint32_t sAhi[BM * 32];      // 8 KB
    __shared__ alignas(16) uint32_t sAlo[BM * 32];      // 8 KB
    __shared__ alignas(16) uint32_t sWhi[W_OUT * 32];   // 8 KB
    __shared__ alignas(16) uint32_t sWlo[W_OUT * 32];   // 8 KB

    const int h  = blockIdx.y;
    const int b0 = blockIdx.x * BM;
    const int t    = threadIdx.x;
    const int wid  = t >> 5;
    const int lane = t & 31;
    const int g  = lane >> 2;
    const int tq = lane & 3;
    const int wm = wid & 1;       // m offset: wm*32
    const int wn = wid >> 1;      // n offset: wn*32

    const bool m64flag = mask_is_i64(mask32);

    const uint32_t aHiBase = smem_u32(sAhi);
    const uint32_t aLoBase = smem_u32(sAlo);
    const uint32_t wHiBase = smem_u32(sWhi);
    const uint32_t wLoBase = smem_u32(sWlo);

    // ldmatrix lane geometry (fragment row offsets are multiples of 8, so the
    // swizzle XOR term is the constant lane&7).
    const int rx   = lane & 7;
    const int a_hi = lane >> 4;           // A: k-chunk +0/+1
    const int b_hi = (lane >> 3) & 1;     // B: k-chunk +0/+1
    uint32_t aRow[2], bRow[2];
#pragma unroll
    for (int mf = 0; mf < 2; ++mf)
        aRow[mf] = (uint32_t)((wm * 32 + mf * 16 + (lane & 15)) * 128);
#pragma unroll
    for (int pr = 0; pr < 2; ++pr)
        bRow[pr] = (uint32_t)((wn * 32 + pr * 16 + (lane & 7) + ((lane >> 4) << 3)) * 128);

    float acc[2][4][4];
#pragma unroll
    for (int a = 0; a < 2; ++a)
#pragma unroll
        for (int b = 0; b < 4; ++b)
#pragma unroll
            for (int c = 0; c < 4; ++c) acc[a][b][c] = 0.0f;

    const float4* xq = reinterpret_cast<const float4*>(x);
    const float4* wq = reinterpret_cast<const float4*>(W);

#pragma unroll
    for (int kc = 0; kc < KSEL; ++kc) {
        const int xrow = mask_val(mask32, m64flag, h * KSEL + kc);

        // ---- stage A: 64 rows x 8 chunks (f32 -> bf16 hi/lo, swizzled) ----
#pragma unroll
        for (int i = 0; i < 4; ++i) {
            int idx = t + i * THREADS;           // 0..511
            int r = idx >> 3, c = idx & 7;
            long f4 = ((long)(b0 + r) * H_IN + xrow) * 16 + c * 2;
            float4 v0 = xq[f4], v1 = xq[f4 + 1];
            uint4 hi, lo;
            cvt8(v0, v1, hi, lo);
            uint32_t off = (uint32_t)(r * 128 + ((c ^ (r & 7)) << 4));
            *reinterpret_cast<uint4*>(reinterpret_cast<char*>(sAhi) + off) = hi;
            *reinterpret_cast<uint4*>(reinterpret_cast<char*>(sAlo) + off) = lo;
        }
        // ---- stage W: 64 rows x 8 chunks ----
#pragma unroll
        for (int i = 0; i < 4; ++i) {
            int idx = t + i * THREADS;           // 0..511
            int r = idx >> 3, c = idx & 7;
            int f4 = (h * 64 + r) * 64 + kc * 16 + c * 2;
            float4 v0 = wq[f4], v1 = wq[f4 + 1];
            uint4 hi, lo;
            cvt8(v0, v1, hi, lo);
            uint32_t off = (uint32_t)(r * 128 + ((c ^ (r & 7)) << 4));
            *reinterpret_cast<uint4*>(reinterpret_cast<char*>(sWhi) + off) = hi;
            *reinterpret_cast<uint4*>(reinterpret_cast<char*>(sWlo) + off) = lo;
        }
        __syncthreads();

        // ---- 4 k16-steps: 8 ldmatrix.x4 + 24 mma each ----
#pragma unroll
        for (int ks = 0; ks < 4; ++ks) {
            uint32_t ah[8], al[8], bh[8], bl[8];
            const int ks2 = ks * 2;
#pragma unroll
            for (int mf = 0; mf < 2; ++mf) {
                uint32_t off = aRow[mf] + (uint32_t)((((ks2 + a_hi) ^ rx)) << 4);
                ldsm4(&ah[mf * 4], aHiBase + off);
                ldsm4(&al[mf * 4], aLoBase + off);
            }
#pragma unroll
            for (int pr = 0; pr < 2; ++pr) {
                uint32_t off = bRow[pr] + (uint32_t)((((ks2 + b_hi) ^ rx)) << 4);
                ldsm4(&bh[pr * 4], wHiBase + off);
                ldsm4(&bl[pr * 4], wLoBase + off);
            }
#pragma unroll
            for (int mf = 0; mf < 2; ++mf)
#pragma unroll
                for (int nf = 0; nf < 4; ++nf) {
                    mma16816(acc[mf][nf], &ah[mf * 4], &bh[nf * 2]);
                    mma16816(acc[mf][nf], &al[mf * 4], &bh[nf * 2]);
                    mma16816(acc[mf][nf], &ah[mf * 4], &bl[nf * 2]);
                }
        }
        __syncthreads();
    }

    // ---- epilogue: add bias, float2 stores ----
#pragma unroll
    for (int nf = 0; nf < 4; ++nf) {
        int col = wn * 32 + nf * 8 + tq * 2;
        float bx = bias[h * W_OUT + col];
        float by = bias[h * W_OUT + col + 1];
#pragma unroll
        for (int mf = 0; mf < 2; ++mf) {
            int row0 = b0 + wm * 32 + mf * 16 + g;
            float2 v0 = {acc[mf][nf][0] + bx, acc[mf][nf][1] + by};
            float2 v1 = {acc[mf][nf][2] + bx, acc[mf][nf][3] + by};
            *reinterpret_cast<float2*>(
                out + ((size_t)row0 * H_OUT + h) * W_OUT + col) = v0;
            *reinterpret_cast<float2*>(
                out + ((size_t)(row0 + 8) * H_OUT + h) * W_OUT + col) = v1;
        }
    }
}

} // namespace asl

extern "C" void kernel_launch(void* const* d_in, const int* in_sizes, int n_in,
                              void* d_out, int out_size) {
    const float* x      = (const float*)d_in[0];
    const int*   mask32 = (const int*)d_in[1];
    const float* W      = (const float*)d_in[2];
    const float* bias   = (const float*)d_in[3];
    float*       out    = (float*)d_out;

    dim3 grid(asl::B_SZ / asl::BM, asl::H_OUT);   // (8, 256)
    asl::fused_kernel<<<grid, asl::THREADS>>>(x, mask32, W, bias, out);
}

// round 10
// speedup vs baseline: 1.1468x; 1.1468x over previous
#include <cuda_runtime.h>
#include <cuda_fp16.h>
#include <cstdint>

// out[b,h,o] = sum_d gathered[b,h,d] * W[h,o,d] + bias[h,o]
// gathered[b,h, 64*k + w] = x[b, mask[h,k], w]
// x:(512,128,64) f32, mask:(256,4) i32 (declared i64; JAX x64-off),
// W:(256,64,256) f32, b:(256,64) f32, out:(512,256,64) f32.
//
// Fused fp16 2-pass GEMM: A split into fp16 hi+lo, W single fp16;
// D = Ahi*Whi + Alo*Whi (fp32 accum). Residual error ~2^-11 on W only
// (~3e-4 rel, threshold 1e-3). CTA m64 x n64, 4 warps of m32 x n32.

namespace asl {

constexpr int B_SZ = 512, H_IN = 128, W_IN = 64, H_OUT = 256, W_OUT = 64;
constexpr int KSEL = 4, D = 256;
constexpr int BM = 64;           // batch rows per CTA
constexpr int THREADS = 128;     // 4 warps, warp tile m32 x n32

__device__ __forceinline__ bool mask_is_i64(const int* m32) {
    int acc = 0;
#pragma unroll
    for (int i = 0; i < 16; ++i) acc |= m32[2 * i + 1];
    return acc == 0;
}
__device__ __forceinline__ int mask_val(const int* m32, bool is64, int idx) {
    int v = is64 ? m32[2 * idx] : m32[idx];
    return min(max(v, 0), H_IN - 1);
}

__device__ __forceinline__ void mma16816(float* c, const uint32_t* a, const uint32_t* b) {
    asm volatile(
        "mma.sync.aligned.m16n8k16.row.col.f32.f16.f16.f32 "
        "{%0,%1,%2,%3}, {%4,%5,%6,%7}, {%8,%9}, {%0,%1,%2,%3};"
        : "+f"(c[0]), "+f"(c[1]), "+f"(c[2]), "+f"(c[3])
        : "r"(a[0]), "r"(a[1]), "r"(a[2]), "r"(a[3]), "r"(b[0]), "r"(b[1]));
}

__device__ __forceinline__ void ldsm4(uint32_t* r, uint32_t saddr) {
    asm volatile("ldmatrix.sync.aligned.m8n8.x4.shared.b16 {%0,%1,%2,%3}, [%4];"
                 : "=r"(r[0]), "=r"(r[1]), "=r"(r[2]), "=r"(r[3]) : "r"(saddr));
}

__device__ __forceinline__ uint32_t smem_u32(const void* p) {
    uint32_t a;
    asm("{ .reg .u64 t; cvta.to.shared.u64 t, %1; cvt.u32.u64 %0, t; }" : "=r"(a) : "l"(p));
    return a;
}

// 8 f32 -> 4x fp16 hi-pairs + 4x fp16 lo-pairs (residuals).
__device__ __forceinline__ void cvt8_split(float4 v0, float4 v1, uint4& hi, uint4& lo) {
    auto one = [](float p, float q, uint32_t& h, uint32_t& l) {
        __half2 hb = __floats2half2_rn(p, q);
        float hp = __low2float(hb), hq = __high2float(hb);
        __half2 lb = __floats2half2_rn(p - hp, q - hq);
        h = *reinterpret_cast<uint32_t*>(&hb);
        l = *reinterpret_cast<uint32_t*>(&lb);
    };
    one(v0.x, v0.y, hi.x, lo.x);
    one(v0.z, v0.w, hi.y, lo.y);
    one(v1.x, v1.y, hi.z, lo.z);
    one(v1.z, v1.w, hi.w, lo.w);
}

// 8 f32 -> 4x fp16 pairs (no residual).
__device__ __forceinline__ void cvt8_single(float4 v0, float4 v1, uint4& hi) {
    auto one = [](float p, float q, uint32_t& h) {
        __half2 hb = __floats2half2_rn(p, q);
        h = *reinterpret_cast<uint32_t*>(&hb);
    };
    one(v0.x, v0.y, hi.x);
    one(v0.z, v0.w, hi.y);
    one(v1.x, v1.y, hi.z);
    one(v1.z, v1.w, hi.w);
}

__global__ __launch_bounds__(THREADS, 4)
void fused_kernel(const float* __restrict__ x,
                  const int* __restrict__ mask32,
                  const float* __restrict__ W,
                  const float* __restrict__ bias,
                  float* __restrict__ out) {
    // Rows of 64 fp16 (128B = 8 chunks of 16B), chunks XOR-swizzled: phys = c ^ (r&7).
    __shared__ alignas(16) uint32_t sAhi[BM * 32];      // 8 KB
    __shared__ alignas(16) uint32_t sAlo[BM * 32];      // 8 KB
    __shared__ alignas(16) uint32_t sWhi[W_OUT * 32];   // 8 KB

    const int h  = blockIdx.y;
    const int b0 = blockIdx.x * BM;
    const int t    = threadIdx.x;
    const int wid  = t >> 5;
    const int lane = t & 31;
    const int g  = lane >> 2;
    const int tq = lane & 3;
    const int wm = wid & 1;       // m offset: wm*32
    const int wn = wid >> 1;      // n offset: wn*32

    const bool m64flag = mask_is_i64(mask32);

    const uint32_t aHiBase = smem_u32(sAhi);
    const uint32_t aLoBase = smem_u32(sAlo);
    const uint32_t wHiBase = smem_u32(sWhi);

    // ldmatrix lane geometry (fragment row offsets are multiples of 8, so the
    // swizzle XOR term is the constant lane&7).
    const int rx   = lane & 7;
    const int a_hi = lane >> 4;           // A: k-chunk +0/+1
    const int b_hi = (lane >> 3) & 1;     // B: k-chunk +0/+1
    uint32_t aRow[2], bRow[2];
#pragma unroll
    for (int mf = 0; mf < 2; ++mf)
        aRow[mf] = (uint32_t)((wm * 32 + mf * 16 + (lane & 15)) * 128);
#pragma unroll
    for (int pr = 0; pr < 2; ++pr)
        bRow[pr] = (uint32_t)((wn * 32 + pr * 16 + (lane & 7) + ((lane >> 4) << 3)) * 128);

    float acc[2][4][4];
#pragma unroll
    for (int a = 0; a < 2; ++a)
#pragma unroll
        for (int b = 0; b < 4; ++b)
#pragma unroll
            for (int c = 0; c < 4; ++c) acc[a][b][c] = 0.0f;

    const float4* xq = reinterpret_cast<const float4*>(x);
    const float4* wq = reinterpret_cast<const float4*>(W);

#pragma unroll
    for (int kc = 0; kc < KSEL; ++kc) {
        const int xrow = mask_val(mask32, m64flag, h * KSEL + kc);

        // ---- stage A: 64 rows x 8 chunks (f32 -> fp16 hi/lo, swizzled) ----
#pragma unroll
        for (int i = 0; i < 4; ++i) {
            int idx = t + i * THREADS;           // 0..511
            int r = idx >> 3, c = idx & 7;
            long f4 = ((long)(b0 + r) * H_IN + xrow) * 16 + c * 2;
            float4 v0 = xq[f4], v1 = xq[f4 + 1];
            uint4 hi, lo;
            cvt8_split(v0, v1, hi, lo);
            uint32_t off = (uint32_t)(r * 128 + ((c ^ (r & 7)) << 4));
            *reinterpret_cast<uint4*>(reinterpret_cast<char*>(sAhi) + off) = hi;
            *reinterpret_cast<uint4*>(reinterpret_cast<char*>(sAlo) + off) = lo;
        }
        // ---- stage W: 64 rows x 8 chunks (f32 -> fp16, swizzled) ----
#pragma unroll
        for (int i = 0; i < 4; ++i) {
            int idx = t + i * THREADS;           // 0..511
            int r = idx >> 3, c = idx & 7;
            int f4 = (h * 64 + r) * 64 + kc * 16 + c * 2;
            float4 v0 = wq[f4], v1 = wq[f4 + 1];
            uint4 hi;
            cvt8_single(v0, v1, hi);
            uint32_t off = (uint32_t)(r * 128 + ((c ^ (r & 7)) << 4));
            *reinterpret_cast<uint4*>(reinterpret_cast<char*>(sWhi) + off) = hi;
        }
        __syncthreads();

        // ---- 4 k16-steps: 6 ldmatrix.x4 + 16 mma each ----
#pragma unroll
        for (int ks = 0; ks < 4; ++ks) {
            uint32_t ah[8], al[8], bh[8];
            const int ks2 = ks * 2;
#pragma unroll
            for (int mf = 0; mf < 2; ++mf) {
                uint32_t off = aRow[mf] + (uint32_t)((((ks2 + a_hi) ^ rx)) << 4);
                ldsm4(&ah[mf * 4], aHiBase + off);
                ldsm4(&al[mf * 4], aLoBase + off);
            }
#pragma unroll
            for (int pr = 0; pr < 2; ++pr) {
                uint32_t off = bRow[pr] + (uint32_t)((((ks2 + b_hi) ^ rx)) << 4);
                ldsm4(&bh[pr * 4], wHiBase + off);
            }
#pragma unroll
            for (int mf = 0; mf < 2; ++mf)
#pragma unroll
                for (int nf = 0; nf < 4; ++nf) {
                    mma16816(acc[mf][nf], &ah[mf * 4], &bh[nf * 2]);
                    mma16816(acc[mf][nf], &al[mf * 4], &bh[nf * 2]);
                }
        }
        __syncthreads();
    }

    // ---- epilogue: add bias, float2 stores ----
#pragma unroll
    for (int nf = 0; nf < 4; ++nf) {
        int col = wn * 32 + nf * 8 + tq * 2;
        float bx = bias[h * W_OUT + col];
        float by = bias[h * W_OUT + col + 1];
#pragma unroll
        for (int mf = 0; mf < 2; ++mf) {
            int row0 = b0 + wm * 32 + mf * 16 + g;
            float2 v0 = {acc[mf][nf][0] + bx, acc[mf][nf][1] + by};
            float2 v1 = {acc[mf][nf][2] + bx, acc[mf][nf][3] + by};
            *reinterpret_cast<float2*>(
                out + ((size_t)row0 * H_OUT + h) * W_OUT + col) = v0;
            *reinterpret_cast<float2*>(
                out + ((size_t)(row0 + 8) * H_OUT + h) * W_OUT + col) = v1;
        }
    }
}

} // namespace asl

extern "C" void kernel_launch(void* const* d_in, const int* in_sizes, int n_in,
                              void* d_out, int out_size) {
    const float* x      = (const float*)d_in[0];
    const int*   mask32 = (const int*)d_in[1];
    const float* W      = (const float*)d_in[2];
    const float* bias   = (const float*)d_in[3];
    float*       out    = (float*)d_out;

    dim3 grid(asl::B_SZ / asl::BM, asl::H_OUT);   // (8, 256)
    asl::fused_kernel<<<grid, asl::THREADS>>>(x, mask32, W, bias, out);
}

// round 11
// speedup vs baseline: 1.4175x; 1.2361x over previous
#include <cuda_runtime.h>
#include <cuda_fp16.h>
#include <cuda.h>
#include <cstdint>

// out[b,h,o] = sum_d gathered[b,h,d] * W[h,o,d] + bias[h,o]
// gathered[b,h, 64*k + w] = x[b, mask[h,k], w]
// x:(512,128,64) f32, mask:(256,4) i32 (declared i64; JAX x64-off),
// W:(256,64,256) f32, b:(256,64) f32, out:(512,256,64) f32.
//
// Two kernels:
//  1) split: x -> fp16 hi/lo scratch, W -> fp16 scratch (device globals).
//  2) gemm: TMA-staged (SW128) fp16 2-pass mma.sync m16n8k16:
//       D = Ahi*Whi + Alo*Whi  (fp32 accum).
//     TMA 3D box performs the x-row gather directly. A double-buffered,
//     W single-buffered, mbarrier expect_tx pipeline.

namespace asl {

constexpr int B_SZ = 512, H_IN = 128, W_IN = 64, H_OUT = 256, W_OUT = 64;
constexpr int KSEL = 4, D = 256;
constexpr int BM = 64;           // batch rows per CTA
constexpr int THREADS = 128;     // 4 warps, warp tile m32 x n32

// fp16 scratch, pair-packed (two consecutive-k elements per uint32).
__device__ alignas(1024) uint32_t g_xhi[B_SZ * H_IN * W_IN / 2];
__device__ alignas(1024) uint32_t g_xlo[B_SZ * H_IN * W_IN / 2];
__device__ alignas(1024) uint32_t g_whi[H_OUT * W_OUT * D / 2];

// ---------------- split kernel ----------------
__device__ __forceinline__ void split4(float4 v, uint2& hi, uint2& lo) {
    __half2 h0 = __floats2half2_rn(v.x, v.y);
    __half2 h1 = __floats2half2_rn(v.z, v.w);
    __half2 l0 = __floats2half2_rn(v.x - __low2float(h0), v.y - __high2float(h0));
    __half2 l1 = __floats2half2_rn(v.z - __low2float(h1), v.w - __high2float(h1));
    hi.x = *reinterpret_cast<uint32_t*>(&h0);
    hi.y = *reinterpret_cast<uint32_t*>(&h1);
    lo.x = *reinterpret_cast<uint32_t*>(&l0);
    lo.y = *reinterpret_cast<uint32_t*>(&l1);
}

__global__ void split_kernel(const float4* __restrict__ x,
                             const float4* __restrict__ w) {
    constexpr int XQ = B_SZ * H_IN * W_IN / 4;   // 1M float4
    constexpr int WQ = H_OUT * W_OUT * D / 4;    // 1M float4
    int i = blockIdx.x * blockDim.x + threadIdx.x;
    int stride = gridDim.x * blockDim.x;
    for (; i < XQ + WQ; i += stride) {
        uint2 hi, lo;
        if (i < XQ) {
            split4(x[i], hi, lo);
            reinterpret_cast<uint2*>(g_xhi)[i] = hi;
            reinterpret_cast<uint2*>(g_xlo)[i] = lo;
        } else {
            split4(w[i - XQ], hi, lo);
            reinterpret_cast<uint2*>(g_whi)[i - XQ] = hi;
        }
    }
}

// ---------------- helpers ----------------
__device__ __forceinline__ bool mask_is_i64(const int* m32) {
    int acc = 0;
#pragma unroll
    for (int i = 0; i < 16; ++i) acc |= m32[2 * i + 1];
    return acc == 0;
}
__device__ __forceinline__ int mask_val(const int* m32, bool is64, int idx) {
    int v = is64 ? m32[2 * idx] : m32[idx];
    return min(max(v, 0), H_IN - 1);
}

__device__ __forceinline__ void mma16816(float* c, const uint32_t* a, const uint32_t* b) {
    asm volatile(
        "mma.sync.aligned.m16n8k16.row.col.f32.f16.f16.f32 "
        "{%0,%1,%2,%3}, {%4,%5,%6,%7}, {%8,%9}, {%0,%1,%2,%3};"
        : "+f"(c[0]), "+f"(c[1]), "+f"(c[2]), "+f"(c[3])
        : "r"(a[0]), "r"(a[1]), "r"(a[2]), "r"(a[3]), "r"(b[0]), "r"(b[1]));
}
__device__ __forceinline__ void ldsm4(uint32_t* r, uint32_t saddr) {
    asm volatile("ldmatrix.sync.aligned.m8n8.x4.shared.b16 {%0,%1,%2,%3}, [%4];"
                 : "=r"(r[0]), "=r"(r[1]), "=r"(r[2]), "=r"(r[3]) : "r"(saddr));
}
__device__ __forceinline__ uint32_t smem_u32(const void* p) {
    uint32_t a;
    asm("{ .reg .u64 t; cvta.to.shared.u64 t, %1; cvt.u32.u64 %0, t; }" : "=r"(a) : "l"(p));
    return a;
}
__device__ __forceinline__ void mbar_init(uint32_t m, uint32_t cnt) {
    asm volatile("mbarrier.init.shared.b64 [%0], %1;" :: "r"(m), "r"(cnt) : "memory");
}
__device__ __forceinline__ void mbar_expect_tx(uint32_t m, uint32_t bytes) {
    asm volatile("mbarrier.arrive.expect_tx.shared.b64 _, [%0], %1;"
                 :: "r"(m), "r"(bytes) : "memory");
}
__device__ __forceinline__ void mbar_wait(uint32_t m, uint32_t parity) {
    asm volatile(
        "{ .reg .pred P;\n"
        "W_%=:\n"
        " mbarrier.try_wait.parity.acquire.cta.shared::cta.b64 P, [%0], %1, 0x989680;\n"
        " @P bra D_%=;\n"
        " bra W_%=;\n"
        "D_%=:\n}"
        :: "r"(m), "r"(parity) : "memory");
}
__device__ __forceinline__ void tma3(uint32_t smem, const CUtensorMap* m,
                                     int c0, int c1, int c2, uint32_t mbar) {
    asm volatile(
        "cp.async.bulk.tensor.3d.shared::cta.global.tile.mbarrier::complete_tx::bytes "
        "[%0], [%1, {%2, %3, %4}], [%5];"
        :: "r"(smem), "l"(m), "r"(c0), "r"(c1), "r"(c2), "r"(mbar) : "memory");
}
__device__ __forceinline__ void tma2(uint32_t smem, const CUtensorMap* m,
                                     int c0, int c1, uint32_t mbar) {
    asm volatile(
        "cp.async.bulk.tensor.2d.shared::cta.global.tile.mbarrier::complete_tx::bytes "
        "[%0], [%1, {%2, %3}], [%4];"
        :: "r"(smem), "l"(m), "r"(c0), "r"(c1), "r"(mbar) : "memory");
}

// ---------------- gemm kernel ----------------
__global__ __launch_bounds__(THREADS)
void gemm_kernel(const __grid_constant__ CUtensorMap mapAhi,
                 const __grid_constant__ CUtensorMap mapAlo,
                 const __grid_constant__ CUtensorMap mapW,
                 const int* __restrict__ mask32,
                 const float* __restrict__ bias,
                 float* __restrict__ out) {
    // SW128 tiles: 64 rows x 128B. TMA's 128B swizzle == chunk c ^ (row&7).
    __shared__ alignas(1024) uint32_t sAhi[2][BM * 32];    // 2 x 8 KB
    __shared__ alignas(1024) uint32_t sAlo[2][BM * 32];    // 2 x 8 KB
    __shared__ alignas(1024) uint32_t sW[W_OUT * 32];      // 8 KB
    __shared__ alignas(8) uint64_t s_mbarA[2];
    __shared__ alignas(8) uint64_t s_mbarW;

    const int h  = blockIdx.y;
    const int b0 = blockIdx.x * BM;
    const int t    = threadIdx.x;
    const int wid  = t >> 5;
    const int lane = t & 31;
    const int g  = lane >> 2;
    const int tq = lane & 3;
    const int wm = wid & 1;       // m offset: wm*32
    const int wn = wid >> 1;      // n offset: wn*32

    const bool m64flag = mask_is_i64(mask32);
    int xrows[KSEL];
#pragma unroll
    for (int k = 0; k < KSEL; ++k) xrows[k] = mask_val(mask32, m64flag, h * KSEL + k);

    const uint32_t aHi0 = smem_u32(sAhi[0]);
    const uint32_t aLo0 = smem_u32(sAlo[0]);
    const uint32_t wBase = smem_u32(sW);
    const uint32_t mbA0 = smem_u32(&s_mbarA[0]);
    const uint32_t mbA1 = smem_u32(&s_mbarA[1]);
    const uint32_t mbW  = smem_u32(&s_mbarW);

    if (t == 0) {
        mbar_init(mbA0, 1);
        mbar_init(mbA1, 1);
        mbar_init(mbW, 1);
    }
    __syncthreads();

    // prologue: chunk 0
    if (t == 0) {
        mbar_expect_tx(mbA0, 16384);
        tma3(aHi0, &mapAhi, 0, xrows[0], b0, mbA0);
        tma3(aLo0, &mapAlo, 0, xrows[0], b0, mbA0);
        mbar_expect_tx(mbW, 8192);
        tma2(wBase, &mapW, 0, h * W_OUT, mbW);
    }

    // ldmatrix lane geometry (row offsets are multiples of 8 -> swizzle XOR
    // term is the constant lane&7).
    const int rx   = lane & 7;
    const int a_hi = lane >> 4;           // A: k-chunk +0/+1
    const int b_hi = (lane >> 3) & 1;     // B: k-chunk +0/+1
    uint32_t aRow[2], bRow[2];
#pragma unroll
    for (int mf = 0; mf < 2; ++mf)
        aRow[mf] = (uint32_t)((wm * 32 + mf * 16 + (lane & 15)) * 128);
#pragma unroll
    for (int pr = 0; pr < 2; ++pr)
        bRow[pr] = (uint32_t)((wn * 32 + pr * 16 + (lane & 7) + ((lane >> 4) << 3)) * 128);

    float acc[2][4][4];
#pragma unroll
    for (int a = 0; a < 2; ++a)
#pragma unroll
        for (int b = 0; b < 4; ++b)
#pragma unroll
            for (int c = 0; c < 4; ++c) acc[a][b][c] = 0.0f;

#pragma unroll
    for (int kc = 0; kc < KSEL; ++kc) {
        const int buf = kc & 1;
        const uint32_t mbA = buf ? mbA1 : mbA0;

        // prefetch A for kc+1 into the other buffer (released at kc-1's sync)
        if (t == 0 && kc + 1 < KSEL) {
            const int nb = buf ^ 1;
            const uint32_t mbAn = nb ? mbA1 : mbA0;
            mbar_expect_tx(mbAn, 16384);
            tma3(aHi0 + nb * 8192, &mapAhi, 0, xrows[kc + 1], b0, mbAn);
            tma3(aLo0 + nb * 8192, &mapAlo, 0, xrows[kc + 1], b0, mbAn);
        }

        mbar_wait(mbA, (kc >> 1) & 1);
        mbar_wait(mbW, kc & 1);

        const uint32_t aHiBase = aHi0 + buf * 8192;
        const uint32_t aLoBase = aLo0 + buf * 8192;

        // ---- 4 k16-steps: 6 ldmatrix.x4 + 16 mma each ----
#pragma unroll
        for (int ks = 0; ks < 4; ++ks) {
            uint32_t ah[8], al[8], bh[8];
            const int ks2 = ks * 2;
#pragma unroll
            for (int mf = 0; mf < 2; ++mf) {
                uint32_t off = aRow[mf] + (uint32_t)((((ks2 + a_hi) ^ rx)) << 4);
                ldsm4(&ah[mf * 4], aHiBase + off);
                ldsm4(&al[mf * 4], aLoBase + off);
            }
#pragma unroll
            for (int pr = 0; pr < 2; ++pr) {
                uint32_t off = bRow[pr] + (uint32_t)((((ks2 + b_hi) ^ rx)) << 4);
                ldsm4(&bh[pr * 4], wBase + off);
            }
#pragma unroll
            for (int mf = 0; mf < 2; ++mf)
#pragma unroll
                for (int nf = 0; nf < 4; ++nf) {
                    mma16816(acc[mf][nf], &ah[mf * 4], &bh[nf * 2]);
                    mma16816(acc[mf][nf], &al[mf * 4], &bh[nf * 2]);
                }
        }
        __syncthreads();   // all warps done with this W tile + A buffer

        // W for kc+1 (single buffer, now safe to overwrite)
        if (t == 0 && kc + 1 < KSEL) {
            mbar_expect_tx(mbW, 8192);
            tma2(wBase, &mapW, (kc + 1) * 64, h * W_OUT, mbW);
        }
    }

    // ---- epilogue: add bias, float2 stores ----
#pragma unroll
    for (int nf = 0; nf < 4; ++nf) {
        int col = wn * 32 + nf * 8 + tq * 2;
        float bx = bias[h * W_OUT + col];
        float by = bias[h * W_OUT + col + 1];
#pragma unroll
        for (int mf = 0; mf < 2; ++mf) {
            int row0 = b0 + wm * 32 + mf * 16 + g;
            float2 v0 = {acc[mf][nf][0] + bx, acc[mf][nf][1] + by};
            float2 v1 = {acc[mf][nf][2] + bx, acc[mf][nf][3] + by};
            *reinterpret_cast<float2*>(
                out + ((size_t)row0 * H_OUT + h) * W_OUT + col) = v0;
            *reinterpret_cast<float2*>(
                out + ((size_t)(row0 + 8) * H_OUT + h) * W_OUT + col) = v1;
        }
    }
}

} // namespace asl

// ---------------- host ----------------
typedef CUresult (*EncodeTiledFn)(
    CUtensorMap*, CUtensorMapDataType, cuuint32_t, void*,
    const cuuint64_t*, const cuuint64_t*, const cuuint32_t*, const cuuint32_t*,
    CUtensorMapInterleave, CUtensorMapSwizzle, CUtensorMapL2promotion,
    CUtensorMapFloatOOBfill);

extern "C" void kernel_launch(void* const* d_in, const int* in_sizes, int n_in,
                              void* d_out, int out_size) {
    const float* x      = (const float*)d_in[0];
    const int*   mask32 = (const int*)d_in[1];
    const float* W      = (const float*)d_in[2];
    const float* bias   = (const float*)d_in[3];
    float*       out    = (float*)d_out;

    // 1) split into fp16 scratch
    asl::split_kernel<<<2048, 256>>>(
        reinterpret_cast<const float4*>(x), reinterpret_cast<const float4*>(W));

    // 2) tensor maps (driver entry point via cudart; no -lcuda needed)
    void* xhi = nullptr; void* xlo = nullptr; void* whi = nullptr;
    cudaGetSymbolAddress(&xhi, asl::g_xhi);
    cudaGetSymbolAddress(&xlo, asl::g_xlo);
    cudaGetSymbolAddress(&whi, asl::g_whi);

    EncodeTiledFn enc = nullptr;
    cudaDriverEntryPointQueryResult qres;
    cudaGetDriverEntryPoint("cuTensorMapEncodeTiled", (void**)&enc,
                            cudaEnableDefault, &qres);

    CUtensorMap mAhi{}, mAlo{}, mW{};
    {
        // x scratch viewed as fp16[512 b][128 hin][64 k]
        cuuint64_t dims[3]    = {64, 128, 512};
        cuuint64_t strides[2] = {128, 128ull * 128};      // bytes
        cuuint32_t box[3]     = {64, 1, 64};
        cuuint32_t es[3]      = {1, 1, 1};
        enc(&mAhi, CU_TENSOR_MAP_DATA_TYPE_FLOAT16, 3, xhi, dims, strides, box, es,
            CU_TENSOR_MAP_INTERLEAVE_NONE, CU_TENSOR_MAP_SWIZZLE_128B,
            CU_TENSOR_MAP_L2_PROMOTION_L2_128B, CU_TENSOR_MAP_FLOAT_OOB_FILL_NONE);
        enc(&mAlo, CU_TENSOR_MAP_DATA_TYPE_FLOAT16, 3, xlo, dims, strides, box, es,
            CU_TENSOR_MAP_INTERLEAVE_NONE, CU_TENSOR_MAP_SWIZZLE_128B,
            CU_TENSOR_MAP_L2_PROMOTION_L2_128B, CU_TENSOR_MAP_FLOAT_OOB_FILL_NONE);
    }
    {
        // W scratch viewed as fp16[256*64 rows][256 k]
        cuuint64_t dims[2]    = {256, 256ull * 64};
        cuuint64_t strides[1] = {512};                    // bytes
        cuuint32_t box[2]     = {64, 64};
        cuuint32_t es[2]      = {1, 1};
        enc(&mW, CU_TENSOR_MAP_DATA_TYPE_FLOAT16, 2, whi, dims, strides, box, es,
            CU_TENSOR_MAP_INTERLEAVE_NONE, CU_TENSOR_MAP_SWIZZLE_128B,
            CU_TENSOR_MAP_L2_PROMOTION_L2_128B, CU_TENSOR_MAP_FLOAT_OOB_FILL_NONE);
    }

    // 3) GEMM
    dim3 grid(asl::B_SZ / asl::BM, asl::H_OUT);   // (8, 256)
    asl::gemm_kernel<<<grid, asl::THREADS>>>(mAhi, mAlo, mW, mask32, bias, out);
}

// round 12
// speedup vs baseline: 1.4792x; 1.0435x over previous
#include <cuda_runtime.h>
#include <cuda_fp16.h>
#include <cuda.h>
#include <cstdint>

// out[b,h,o] = sum_d gathered[b,h,d] * W[h,o,d] + bias[h,o]
// gathered[b,h, 64*k + w] = x[b, mask[h,k], w]
// x:(512,128,64) f32, mask:(256,4) i32 (declared i64; JAX x64-off),
// W:(256,64,256) f32, b:(256,64) f32, out:(512,256,64) f32.
//
// 1) split: x -> fp16 hi/lo scratch, W -> fp16 scratch.
// 2) gemm: fully double-buffered TMA pipeline (A hi/lo + W behind ONE
//    mbarrier per stage), fp16 2-pass mma.sync m16n8k16:
//    D = Ahi*Whi + Alo*Whi (fp32 accum).

namespace asl {

constexpr int B_SZ = 512, H_IN = 128, W_IN = 64, H_OUT = 256, W_OUT = 64;
constexpr int KSEL = 4, D = 256;
constexpr int BM = 64;           // batch rows per CTA
constexpr int THREADS = 128;     // 4 warps, warp tile m32 x n32

// fp16 scratch, pair-packed.
__device__ alignas(1024) uint32_t g_xhi[B_SZ * H_IN * W_IN / 2];
__device__ alignas(1024) uint32_t g_xlo[B_SZ * H_IN * W_IN / 2];
__device__ alignas(1024) uint32_t g_whi[H_OUT * W_OUT * D / 2];

// ---------------- split kernel ----------------
__device__ __forceinline__ void split4(float4 v, uint2& hi, uint2& lo) {
    __half2 h0 = __floats2half2_rn(v.x, v.y);
    __half2 h1 = __floats2half2_rn(v.z, v.w);
    __half2 l0 = __floats2half2_rn(v.x - __low2float(h0), v.y - __high2float(h0));
    __half2 l1 = __floats2half2_rn(v.z - __low2float(h1), v.w - __high2float(h1));
    hi.x = *reinterpret_cast<uint32_t*>(&h0);
    hi.y = *reinterpret_cast<uint32_t*>(&h1);
    lo.x = *reinterpret_cast<uint32_t*>(&l0);
    lo.y = *reinterpret_cast<uint32_t*>(&l1);
}

__global__ void split_kernel(const float4* __restrict__ x,
                             const float4* __restrict__ w) {
    constexpr int XQ = B_SZ * H_IN * W_IN / 4;
    constexpr int WQ = H_OUT * W_OUT * D / 4;
    int i = blockIdx.x * blockDim.x + threadIdx.x;
    int stride = gridDim.x * blockDim.x;
    for (; i < XQ + WQ; i += stride) {
        uint2 hi, lo;
        if (i < XQ) {
            split4(x[i], hi, lo);
            reinterpret_cast<uint2*>(g_xhi)[i] = hi;
            reinterpret_cast<uint2*>(g_xlo)[i] = lo;
        } else {
            split4(w[i - XQ], hi, lo);
            reinterpret_cast<uint2*>(g_whi)[i - XQ] = hi;
        }
    }
}

// ---------------- helpers ----------------
__device__ __forceinline__ bool mask_is_i64(const int* m32) {
    int acc = 0;
#pragma unroll
    for (int i = 0; i < 16; ++i) acc |= m32[2 * i + 1];
    return acc == 0;
}
__device__ __forceinline__ int mask_val(const int* m32, bool is64, int idx) {
    int v = is64 ? m32[2 * idx] : m32[idx];
    return min(max(v, 0), H_IN - 1);
}
__device__ __forceinline__ void mma16816(float* c, const uint32_t* a, const uint32_t* b) {
    asm volatile(
        "mma.sync.aligned.m16n8k16.row.col.f32.f16.f16.f32 "
        "{%0,%1,%2,%3}, {%4,%5,%6,%7}, {%8,%9}, {%0,%1,%2,%3};"
        : "+f"(c[0]), "+f"(c[1]), "+f"(c[2]), "+f"(c[3])
        : "r"(a[0]), "r"(a[1]), "r"(a[2]), "r"(a[3]), "r"(b[0]), "r"(b[1]));
}
__device__ __forceinline__ void ldsm4(uint32_t* r, uint32_t saddr) {
    asm volatile("ldmatrix.sync.aligned.m8n8.x4.shared.b16 {%0,%1,%2,%3}, [%4];"
                 : "=r"(r[0]), "=r"(r[1]), "=r"(r[2]), "=r"(r[3]) : "r"(saddr));
}
__device__ __forceinline__ uint32_t smem_u32(const void* p) {
    uint32_t a;
    asm("{ .reg .u64 t; cvta.to.shared.u64 t, %1; cvt.u32.u64 %0, t; }" : "=r"(a) : "l"(p));
    return a;
}
__device__ __forceinline__ void mbar_init(uint32_t m, uint32_t cnt) {
    asm volatile("mbarrier.init.shared.b64 [%0], %1;" :: "r"(m), "r"(cnt) : "memory");
}
__device__ __forceinline__ void mbar_expect_tx(uint32_t m, uint32_t bytes) {
    asm volatile("mbarrier.arrive.expect_tx.shared.b64 _, [%0], %1;"
                 :: "r"(m), "r"(bytes) : "memory");
}
__device__ __forceinline__ void mbar_wait(uint32_t m, uint32_t parity) {
    asm volatile(
        "{ .reg .pred P;\n"
        "W_%=:\n"
        " mbarrier.try_wait.parity.acquire.cta.shared::cta.b64 P, [%0], %1, 0x989680;\n"
        " @P bra D_%=;\n"
        " bra W_%=;\n"
        "D_%=:\n}"
        :: "r"(m), "r"(parity) : "memory");
}
__device__ __forceinline__ void tma3(uint32_t smem, const CUtensorMap* m,
                                     int c0, int c1, int c2, uint32_t mbar) {
    asm volatile(
        "cp.async.bulk.tensor.3d.shared::cta.global.tile.mbarrier::complete_tx::bytes "
        "[%0], [%1, {%2, %3, %4}], [%5];"
        :: "r"(smem), "l"(m), "r"(c0), "r"(c1), "r"(c2), "r"(mbar) : "memory");
}
__device__ __forceinline__ void tma2(uint32_t smem, const CUtensorMap* m,
                                     int c0, int c1, uint32_t mbar) {
    asm volatile(
        "cp.async.bulk.tensor.2d.shared::cta.global.tile.mbarrier::complete_tx::bytes "
        "[%0], [%1, {%2, %3}], [%4];"
        :: "r"(smem), "l"(m), "r"(c0), "r"(c1), "r"(mbar) : "memory");
}

// ---------------- gemm kernel ----------------
__global__ __launch_bounds__(THREADS)
void gemm_kernel(const __grid_constant__ CUtensorMap mapAhi,
                 const __grid_constant__ CUtensorMap mapAlo,
                 const __grid_constant__ CUtensorMap mapW,
                 const int* __restrict__ mask32,
                 const float* __restrict__ bias,
                 float* __restrict__ out) {
    // Two full stages: each = A hi (8K) + A lo (8K) + W (8K), one mbarrier.
    __shared__ alignas(1024) uint32_t sAhi[2][BM * 32];
    __shared__ alignas(1024) uint32_t sAlo[2][BM * 32];
    __shared__ alignas(1024) uint32_t sW[2][W_OUT * 32];
    __shared__ alignas(8) uint64_t s_mbar[2];

    const int h  = blockIdx.y;
    const int b0 = blockIdx.x * BM;
    const int t    = threadIdx.x;
    const int wid  = t >> 5;
    const int lane = t & 31;
    const int g  = lane >> 2;
    const int tq = lane & 3;
    const int wm = wid & 1;
    const int wn = wid >> 1;

    const bool m64flag = mask_is_i64(mask32);
    int xrows[KSEL];
#pragma unroll
    for (int k = 0; k < KSEL; ++k) xrows[k] = mask_val(mask32, m64flag, h * KSEL + k);

    const uint32_t aHi0 = smem_u32(sAhi[0]);
    const uint32_t aLo0 = smem_u32(sAlo[0]);
    const uint32_t w0   = smem_u32(sW[0]);
    uint32_t mb[2] = {smem_u32(&s_mbar[0]), smem_u32(&s_mbar[1])};

    if (t == 0) {
        mbar_init(mb[0], 1);
        mbar_init(mb[1], 1);
    }
    __syncthreads();

    // prologue: stage 0 (A hi + A lo + W, one barrier, 24576 bytes)
    if (t == 0) {
        mbar_expect_tx(mb[0], 24576);
        tma3(aHi0, &mapAhi, 0, xrows[0], b0, mb[0]);
        tma3(aLo0, &mapAlo, 0, xrows[0], b0, mb[0]);
        tma2(w0, &mapW, 0, h * W_OUT, mb[0]);
    }

    // ldmatrix lane geometry (row offsets are multiples of 8 -> swizzle XOR
    // term is the constant lane&7).
    const int rx   = lane & 7;
    const int a_hi = lane >> 4;
    const int b_hi = (lane >> 3) & 1;
    uint32_t aRow[2], bRow[2];
#pragma unroll
    for (int mf = 0; mf < 2; ++mf)
        aRow[mf] = (uint32_t)((wm * 32 + mf * 16 + (lane & 15)) * 128);
#pragma unroll
    for (int pr = 0; pr < 2; ++pr)
        bRow[pr] = (uint32_t)((wn * 32 + pr * 16 + (lane & 7) + ((lane >> 4) << 3)) * 128);

    float acc[2][4][4];
#pragma unroll
    for (int a = 0; a < 2; ++a)
#pragma unroll
        for (int b = 0; b < 4; ++b)
#pragma unroll
            for (int c = 0; c < 4; ++c) acc[a][b][c] = 0.0f;

#pragma unroll
    for (int kc = 0; kc < KSEL; ++kc) {
        const int buf = kc & 1;

        // Prefetch stage kc+1 into the other buffer. That buffer was last
        // used by kc-1 and released by the __syncthreads ending chunk kc-1.
        if (t == 0 && kc + 1 < KSEL) {
            const int nb = buf ^ 1;
            mbar_expect_tx(mb[nb], 24576);
            tma3(aHi0 + nb * 8192, &mapAhi, 0, xrows[kc + 1], b0, mb[nb]);
            tma3(aLo0 + nb * 8192, &mapAlo, 0, xrows[kc + 1], b0, mb[nb]);
            tma2(w0 + nb * 8192, &mapW, (kc + 1) * 64, h * W_OUT, mb[nb]);
        }

        mbar_wait(mb[buf], (kc >> 1) & 1);

        const uint32_t aHiBase = aHi0 + buf * 8192;
        const uint32_t aLoBase = aLo0 + buf * 8192;
        const uint32_t wBase   = w0 + buf * 8192;

        // ---- 4 k16-steps: 6 ldmatrix.x4 + 16 mma each ----
#pragma unroll
        for (int ks = 0; ks < 4; ++ks) {
            uint32_t ah[8], al[8], bh[8];
            const int ks2 = ks * 2;
#pragma unroll
            for (int mf = 0; mf < 2; ++mf) {
                uint32_t off = aRow[mf] + (uint32_t)((((ks2 + a_hi) ^ rx)) << 4);
                ldsm4(&ah[mf * 4], aHiBase + off);
                ldsm4(&al[mf * 4], aLoBase + off);
            }
#pragma unroll
            for (int pr = 0; pr < 2; ++pr) {
                uint32_t off = bRow[pr] + (uint32_t)((((ks2 + b_hi) ^ rx)) << 4);
                ldsm4(&bh[pr * 4], wBase + off);
            }
#pragma unroll
            for (int mf = 0; mf < 2; ++mf)
#pragma unroll
                for (int nf = 0; nf < 4; ++nf) {
                    mma16816(acc[mf][nf], &ah[mf * 4], &bh[nf * 2]);
                    mma16816(acc[mf][nf], &al[mf * 4], &bh[nf * 2]);
                }
        }
        __syncthreads();   // release this stage's buffers for kc+2's prefetch
    }

    // ---- epilogue: add bias, float2 stores ----
#pragma unroll
    for (int nf = 0; nf < 4; ++nf) {
        int col = wn * 32 + nf * 8 + tq * 2;
        float bx = bias[h * W_OUT + col];
        float by = bias[h * W_OUT + col + 1];
#pragma unroll
        for (int mf = 0; mf < 2; ++mf) {
            int row0 = b0 + wm * 32 + mf * 16 + g;
            float2 v0 = {acc[mf][nf][0] + bx, acc[mf][nf][1] + by};
            float2 v1 = {acc[mf][nf][2] + bx, acc[mf][nf][3] + by};
            *reinterpret_cast<float2*>(
                out + ((size_t)row0 * H_OUT + h) * W_OUT + col) = v0;
            *reinterpret_cast<float2*>(
                out + ((size_t)(row0 + 8) * H_OUT + h) * W_OUT + col) = v1;
        }
    }
}

} // namespace asl

// ---------------- host ----------------
typedef CUresult (*EncodeTiledFn)(
    CUtensorMap*, CUtensorMapDataType, cuuint32_t, void*,
    const cuuint64_t*, const cuuint64_t*, const cuuint32_t*, const cuuint32_t*,
    CUtensorMapInterleave, CUtensorMapSwizzle, CUtensorMapL2promotion,
    CUtensorMapFloatOOBfill);

extern "C" void kernel_launch(void* const* d_in, const int* in_sizes, int n_in,
                              void* d_out, int out_size) {
    const float* x      = (const float*)d_in[0];
    const int*   mask32 = (const int*)d_in[1];
    const float* W      = (const float*)d_in[2];
    const float* bias   = (const float*)d_in[3];
    float*       out    = (float*)d_out;

    asl::split_kernel<<<2048, 256>>>(
        reinterpret_cast<const float4*>(x), reinterpret_cast<const float4*>(W));

    void* xhi = nullptr; void* xlo = nullptr; void* whi = nullptr;
    cudaGetSymbolAddress(&xhi, asl::g_xhi);
    cudaGetSymbolAddress(&xlo, asl::g_xlo);
    cudaGetSymbolAddress(&whi, asl::g_whi);

    EncodeTiledFn enc = nullptr;
    cudaDriverEntryPointQueryResult qres;
    cudaGetDriverEntryPoint("cuTensorMapEncodeTiled", (void**)&enc,
                            cudaEnableDefault, &qres);

    CUtensorMap mAhi{}, mAlo{}, mW{};
    {
        cuuint64_t dims[3]    = {64, 128, 512};
        cuuint64_t strides[2] = {128, 128ull * 128};
        cuuint32_t box[3]     = {64, 1, 64};
        cuuint32_t es[3]      = {1, 1, 1};
        enc(&mAhi, CU_TENSOR_MAP_DATA_TYPE_FLOAT16, 3, xhi, dims, strides, box, es,
            CU_TENSOR_MAP_INTERLEAVE_NONE, CU_TENSOR_MAP_SWIZZLE_128B,
            CU_TENSOR_MAP_L2_PROMOTION_L2_128B, CU_TENSOR_MAP_FLOAT_OOB_FILL_NONE);
        enc(&mAlo, CU_TENSOR_MAP_DATA_TYPE_FLOAT16, 3, xlo, dims, strides, box, es,
            CU_TENSOR_MAP_INTERLEAVE_NONE, CU_TENSOR_MAP_SWIZZLE_128B,
            CU_TENSOR_MAP_L2_PROMOTION_L2_128B, CU_TENSOR_MAP_FLOAT_OOB_FILL_NONE);
    }
    {
        cuuint64_t dims[2]    = {256, 256ull * 64};
        cuuint64_t strides[1] = {512};
        cuuint32_t box[2]     = {64, 64};
        cuuint32_t es[2]      = {1, 1};
        enc(&mW, CU_TENSOR_MAP_DATA_TYPE_FLOAT16, 2, whi, dims, strides, box, es,
            CU_TENSOR_MAP_INTERLEAVE_NONE, CU_TENSOR_MAP_SWIZZLE_128B,
            CU_TENSOR_MAP_L2_PROMOTION_L2_128B, CU_TENSOR_MAP_FLOAT_OOB_FILL_NONE);
    }

    dim3 grid(asl::B_SZ / asl::BM, asl::H_OUT);   // (8, 256)
    asl::gemm_kernel<<<grid, asl::THREADS>>>(mAhi, mAlo, mW, mask32, bias, out);
}

// round 13
// speedup vs baseline: 1.9280x; 1.3034x over previous
#include <cuda_runtime.h>
#include <cuda_fp16.h>
#include <cuda.h>
#include <cstdint>

// out[b,h,o] = sum_d gathered[b,h,d] * W[h,o,d] + bias[h,o]
// gathered[b,h, 64*k + w] = x[b, mask[h,k], w]
// x:(512,128,64) f32, mask:(256,4) i32 (declared i64; JAX x64-off),
// W:(256,64,256) f32, b:(256,64) f32, out:(512,256,64) f32.
//
// 1) split: x, W -> fp16 scratch (single precision pass).
// 2) gemm: double-buffered TMA pipeline (A + W behind one mbarrier/stage),
//    single-pass fp16 mma.sync m16n8k16, fp32 accum.
//    Error: ~2.9e-4 rel (W-only rounding measured 2.06e-4; A adds ~sqrt2x).

namespace asl {

constexpr int B_SZ = 512, H_IN = 128, W_IN = 64, H_OUT = 256, W_OUT = 64;
constexpr int KSEL = 4, D = 256;
constexpr int BM = 64;           // batch rows per CTA
constexpr int THREADS = 128;     // 4 warps, warp tile m32 x n32

// fp16 scratch, pair-packed.
__device__ alignas(1024) uint32_t g_xhi[B_SZ * H_IN * W_IN / 2];
__device__ alignas(1024) uint32_t g_whi[H_OUT * W_OUT * D / 2];

// ---------------- split kernel ----------------
__device__ __forceinline__ uint2 cvt4(float4 v) {
    __half2 h0 = __floats2half2_rn(v.x, v.y);
    __half2 h1 = __floats2half2_rn(v.z, v.w);
    uint2 r;
    r.x = *reinterpret_cast<uint32_t*>(&h0);
    r.y = *reinterpret_cast<uint32_t*>(&h1);
    return r;
}

__global__ void split_kernel(const float4* __restrict__ x,
                             const float4* __restrict__ w) {
    constexpr int XQ = B_SZ * H_IN * W_IN / 4;
    constexpr int WQ = H_OUT * W_OUT * D / 4;
    int i = blockIdx.x * blockDim.x + threadIdx.x;
    int stride = gridDim.x * blockDim.x;
    for (; i < XQ + WQ; i += stride) {
        if (i < XQ)
            reinterpret_cast<uint2*>(g_xhi)[i] = cvt4(x[i]);
        else
            reinterpret_cast<uint2*>(g_whi)[i - XQ] = cvt4(w[i - XQ]);
    }
}

// ---------------- helpers ----------------
__device__ __forceinline__ bool mask_is_i64(const int* m32) {
    int acc = 0;
#pragma unroll
    for (int i = 0; i < 16; ++i) acc |= m32[2 * i + 1];
    return acc == 0;
}
__device__ __forceinline__ int mask_val(const int* m32, bool is64, int idx) {
    int v = is64 ? m32[2 * idx] : m32[idx];
    return min(max(v, 0), H_IN - 1);
}
__device__ __forceinline__ void mma16816(float* c, const uint32_t* a, const uint32_t* b) {
    asm volatile(
        "mma.sync.aligned.m16n8k16.row.col.f32.f16.f16.f32 "
        "{%0,%1,%2,%3}, {%4,%5,%6,%7}, {%8,%9}, {%0,%1,%2,%3};"
        : "+f"(c[0]), "+f"(c[1]), "+f"(c[2]), "+f"(c[3])
        : "r"(a[0]), "r"(a[1]), "r"(a[2]), "r"(a[3]), "r"(b[0]), "r"(b[1]));
}
__device__ __forceinline__ void ldsm4(uint32_t* r, uint32_t saddr) {
    asm volatile("ldmatrix.sync.aligned.m8n8.x4.shared.b16 {%0,%1,%2,%3}, [%4];"
                 : "=r"(r[0]), "=r"(r[1]), "=r"(r[2]), "=r"(r[3]) : "r"(saddr));
}
__device__ __forceinline__ uint32_t smem_u32(const void* p) {
    uint32_t a;
    asm("{ .reg .u64 t; cvta.to.shared.u64 t, %1; cvt.u32.u64 %0, t; }" : "=r"(a) : "l"(p));
    return a;
}
__device__ __forceinline__ void mbar_init(uint32_t m, uint32_t cnt) {
    asm volatile("mbarrier.init.shared.b64 [%0], %1;" :: "r"(m), "r"(cnt) : "memory");
}
__device__ __forceinline__ void mbar_expect_tx(uint32_t m, uint32_t bytes) {
    asm volatile("mbarrier.arrive.expect_tx.shared.b64 _, [%0], %1;"
                 :: "r"(m), "r"(bytes) : "memory");
}
__device__ __forceinline__ void mbar_wait(uint32_t m, uint32_t parity) {
    asm volatile(
        "{ .reg .pred P;\n"
        "W_%=:\n"
        " mbarrier.try_wait.parity.acquire.cta.shared::cta.b64 P, [%0], %1, 0x989680;\n"
        " @P bra D_%=;\n"
        " bra W_%=;\n"
        "D_%=:\n}"
        :: "r"(m), "r"(parity) : "memory");
}
__device__ __forceinline__ void tma3(uint32_t smem, const CUtensorMap* m,
                                     int c0, int c1, int c2, uint32_t mbar) {
    asm volatile(
        "cp.async.bulk.tensor.3d.shared::cta.global.tile.mbarrier::complete_tx::bytes "
        "[%0], [%1, {%2, %3, %4}], [%5];"
        :: "r"(smem), "l"(m), "r"(c0), "r"(c1), "r"(c2), "r"(mbar) : "memory");
}
__device__ __forceinline__ void tma2(uint32_t smem, const CUtensorMap* m,
                                     int c0, int c1, uint32_t mbar) {
    asm volatile(
        "cp.async.bulk.tensor.2d.shared::cta.global.tile.mbarrier::complete_tx::bytes "
        "[%0], [%1, {%2, %3}], [%4];"
        :: "r"(smem), "l"(m), "r"(c0), "r"(c1), "r"(mbar) : "memory");
}

// ---------------- gemm kernel ----------------
__global__ __launch_bounds__(THREADS)
void gemm_kernel(const __grid_constant__ CUtensorMap mapA,
                 const __grid_constant__ CUtensorMap mapW,
                 const int* __restrict__ mask32,
                 const float* __restrict__ bias,
                 float* __restrict__ out) {
    // Two stages: each = A (8K) + W (8K), one mbarrier (16384 bytes).
    __shared__ alignas(1024) uint32_t sA[2][BM * 32];
    __shared__ alignas(1024) uint32_t sW[2][W_OUT * 32];
    __shared__ alignas(8) uint64_t s_mbar[2];

    const int h  = blockIdx.y;
    const int b0 = blockIdx.x * BM;
    const int t    = threadIdx.x;
    const int wid  = t >> 5;
    const int lane = t & 31;
    const int g  = lane >> 2;
    const int tq = lane & 3;
    const int wm = wid & 1;
    const int wn = wid >> 1;

    const bool m64flag = mask_is_i64(mask32);
    int xrows[KSEL];
#pragma unroll
    for (int k = 0; k < KSEL; ++k) xrows[k] = mask_val(mask32, m64flag, h * KSEL + k);

    const uint32_t a0 = smem_u32(sA[0]);
    const uint32_t w0 = smem_u32(sW[0]);
    uint32_t mb[2] = {smem_u32(&s_mbar[0]), smem_u32(&s_mbar[1])};

    if (t == 0) {
        mbar_init(mb[0], 1);
        mbar_init(mb[1], 1);
    }
    __syncthreads();

    // prologue: stage 0
    if (t == 0) {
        mbar_expect_tx(mb[0], 16384);
        tma3(a0, &mapA, 0, xrows[0], b0, mb[0]);
        tma2(w0, &mapW, 0, h * W_OUT, mb[0]);
    }

    // ldmatrix lane geometry (row offsets are multiples of 8 -> swizzle XOR
    // term is the constant lane&7).
    const int rx   = lane & 7;
    const int a_hi = lane >> 4;
    const int b_hi = (lane >> 3) & 1;
    uint32_t aRow[2], bRow[2];
#pragma unroll
    for (int mf = 0; mf < 2; ++mf)
        aRow[mf] = (uint32_t)((wm * 32 + mf * 16 + (lane & 15)) * 128);
#pragma unroll
    for (int pr = 0; pr < 2; ++pr)
        bRow[pr] = (uint32_t)((wn * 32 + pr * 16 + (lane & 7) + ((lane >> 4) << 3)) * 128);

    float acc[2][4][4];
#pragma unroll
    for (int a = 0; a < 2; ++a)
#pragma unroll
        for (int b = 0; b < 4; ++b)
#pragma unroll
            for (int c = 0; c < 4; ++c) acc[a][b][c] = 0.0f;

#pragma unroll
    for (int kc = 0; kc < KSEL; ++kc) {
        const int buf = kc & 1;

        // prefetch stage kc+1 (buffer freed by the sync ending chunk kc-1)
        if (t == 0 && kc + 1 < KSEL) {
            const int nb = buf ^ 1;
            mbar_expect_tx(mb[nb], 16384);
            tma3(a0 + nb * 8192, &mapA, 0, xrows[kc + 1], b0, mb[nb]);
            tma2(w0 + nb * 8192, &mapW, (kc + 1) * 64, h * W_OUT, mb[nb]);
        }

        mbar_wait(mb[buf], (kc >> 1) & 1);

        const uint32_t aBase = a0 + buf * 8192;
        const uint32_t wBase = w0 + buf * 8192;

        // ---- 4 k16-steps: 4 ldmatrix.x4 + 8 mma each ----
#pragma unroll
        for (int ks = 0; ks < 4; ++ks) {
            uint32_t ah[8], bh[8];
            const int ks2 = ks * 2;
#pragma unroll
            for (int mf = 0; mf < 2; ++mf) {
                uint32_t off = aRow[mf] + (uint32_t)((((ks2 + a_hi) ^ rx)) << 4);
                ldsm4(&ah[mf * 4], aBase + off);
            }
#pragma unroll
            for (int pr = 0; pr < 2; ++pr) {
                uint32_t off = bRow[pr] + (uint32_t)((((ks2 + b_hi) ^ rx)) << 4);
                ldsm4(&bh[pr * 4], wBase + off);
            }
#pragma unroll
            for (int mf = 0; mf < 2; ++mf)
#pragma unroll
                for (int nf = 0; nf < 4; ++nf)
                    mma16816(acc[mf][nf], &ah[mf * 4], &bh[nf * 2]);
        }
        __syncthreads();   // release this stage for kc+2's prefetch
    }

    // ---- epilogue: add bias, float2 stores ----
#pragma unroll
    for (int nf = 0; nf < 4; ++nf) {
        int col = wn * 32 + nf * 8 + tq * 2;
        float bx = bias[h * W_OUT + col];
        float by = bias[h * W_OUT + col + 1];
#pragma unroll
        for (int mf = 0; mf < 2; ++mf) {
            int row0 = b0 + wm * 32 + mf * 16 + g;
            float2 v0 = {acc[mf][nf][0] + bx, acc[mf][nf][1] + by};
            float2 v1 = {acc[mf][nf][2] + bx, acc[mf][nf][3] + by};
            *reinterpret_cast<float2*>(
                out + ((size_t)row0 * H_OUT + h) * W_OUT + col) = v0;
            *reinterpret_cast<float2*>(
                out + ((size_t)(row0 + 8) * H_OUT + h) * W_OUT + col) = v1;
        }
    }
}

} // namespace asl

// ---------------- host ----------------
typedef CUresult (*EncodeTiledFn)(
    CUtensorMap*, CUtensorMapDataType, cuuint32_t, void*,
    const cuuint64_t*, const cuuint64_t*, const cuuint32_t*, const cuuint32_t*,
    CUtensorMapInterleave, CUtensorMapSwizzle, CUtensorMapL2promotion,
    CUtensorMapFloatOOBfill);

extern "C" void kernel_launch(void* const* d_in, const int* in_sizes, int n_in,
                              void* d_out, int out_size) {
    const float* x      = (const float*)d_in[0];
    const int*   mask32 = (const int*)d_in[1];
    const float* W      = (const float*)d_in[2];
    const float* bias   = (const float*)d_in[3];
    float*       out    = (float*)d_out;

    asl::split_kernel<<<2048, 256>>>(
        reinterpret_cast<const float4*>(x), reinterpret_cast<const float4*>(W));

    void* xhi = nullptr; void* whi = nullptr;
    cudaGetSymbolAddress(&xhi, asl::g_xhi);
    cudaGetSymbolAddress(&whi, asl::g_whi);

    EncodeTiledFn enc = nullptr;
    cudaDriverEntryPointQueryResult qres;
    cudaGetDriverEntryPoint("cuTensorMapEncodeTiled", (void**)&enc,
                            cudaEnableDefault, &qres);

    CUtensorMap mA{}, mW{};
    {
        cuuint64_t dims[3]    = {64, 128, 512};
        cuuint64_t strides[2] = {128, 128ull * 128};
        cuuint32_t box[3]     = {64, 1, 64};
        cuuint32_t es[3]      = {1, 1, 1};
        enc(&mA, CU_TENSOR_MAP_DATA_TYPE_FLOAT16, 3, xhi, dims, strides, box, es,
            CU_TENSOR_MAP_INTERLEAVE_NONE, CU_TENSOR_MAP_SWIZZLE_128B,
            CU_TENSOR_MAP_L2_PROMOTION_L2_128B, CU_TENSOR_MAP_FLOAT_OOB_FILL_NONE);
    }
    {
        cuuint64_t dims[2]    = {256, 256ull * 64};
        cuuint64_t strides[1] = {512};
        cuuint32_t box[2]     = {64, 64};
        cuuint32_t es[2]      = {1, 1};
        enc(&mW, CU_TENSOR_MAP_DATA_TYPE_FLOAT16, 2, whi, dims, strides, box, es,
            CU_TENSOR_MAP_INTERLEAVE_NONE, CU_TENSOR_MAP_SWIZZLE_128B,
            CU_TENSOR_MAP_L2_PROMOTION_L2_128B, CU_TENSOR_MAP_FLOAT_OOB_FILL_NONE);
    }

    dim3 grid(asl::B_SZ / asl::BM, asl::H_OUT);   // (8, 256)
    asl::gemm_kernel<<<grid, asl::THREADS>>>(mA, mW, mask32, bias, out);
}

// round 14
// speedup vs baseline: 2.0856x; 1.0817x over previous
#include <cuda_runtime.h>
#include <cuda_fp16.h>
#include <cuda.h>
#include <cstdint>

// out[b,h,o] = sum_d gathered[b,h,d] * W[h,o,d] + bias[h,o]
// gathered[b,h, 64*k + w] = x[b, mask[h,k], w]
// x:(512,128,64) f32, mask:(256,4) i32 (declared i64; JAX x64-off),
// W:(256,64,256) f32, b:(256,64) f32, out:(512,256,64) f32.
//
// 1) split: x, W -> fp16 scratch.
// 2) gemm: CTA m128 x n64 (4 warps), each warp = two m32 sub-tiles sharing
//    B fragments (0.375 LDSM per MMA). A TMA double-buffered, W single.
//    Single-pass fp16 mma.sync m16n8k16, fp32 accum (~2.9e-4 rel err).

namespace asl {

constexpr int B_SZ = 512, H_IN = 128, W_IN = 64, H_OUT = 256, W_OUT = 64;
constexpr int KSEL = 4, D = 256;
constexpr int BM = 128;          // batch rows per CTA
constexpr int THREADS = 128;     // 4 warps

// fp16 scratch, pair-packed.
__device__ alignas(1024) uint32_t g_xhi[B_SZ * H_IN * W_IN / 2];
__device__ alignas(1024) uint32_t g_whi[H_OUT * W_OUT * D / 2];

// ---------------- split kernel ----------------
__device__ __forceinline__ uint2 cvt4(float4 v) {
    __half2 h0 = __floats2half2_rn(v.x, v.y);
    __half2 h1 = __floats2half2_rn(v.z, v.w);
    uint2 r;
    r.x = *reinterpret_cast<uint32_t*>(&h0);
    r.y = *reinterpret_cast<uint32_t*>(&h1);
    return r;
}

__global__ void split_kernel(const float4* __restrict__ x,
                             const float4* __restrict__ w) {
    constexpr int XQ = B_SZ * H_IN * W_IN / 4;
    constexpr int WQ = H_OUT * W_OUT * D / 4;
    int i = blockIdx.x * blockDim.x + threadIdx.x;
    int stride = gridDim.x * blockDim.x;
    for (; i < XQ + WQ; i += stride) {
        if (i < XQ)
            reinterpret_cast<uint2*>(g_xhi)[i] = cvt4(x[i]);
        else
            reinterpret_cast<uint2*>(g_whi)[i - XQ] = cvt4(w[i - XQ]);
    }
}

// ---------------- helpers ----------------
__device__ __forceinline__ bool mask_is_i64(const int* m32) {
    int acc = 0;
#pragma unroll
    for (int i = 0; i < 16; ++i) acc |= m32[2 * i + 1];
    return acc == 0;
}
__device__ __forceinline__ int mask_val(const int* m32, bool is64, int idx) {
    int v = is64 ? m32[2 * idx] : m32[idx];
    return min(max(v, 0), H_IN - 1);
}
__device__ __forceinline__ void mma16816(float* c, const uint32_t* a, const uint32_t* b) {
    asm volatile(
        "mma.sync.aligned.m16n8k16.row.col.f32.f16.f16.f32 "
        "{%0,%1,%2,%3}, {%4,%5,%6,%7}, {%8,%9}, {%0,%1,%2,%3};"
        : "+f"(c[0]), "+f"(c[1]), "+f"(c[2]), "+f"(c[3])
        : "r"(a[0]), "r"(a[1]), "r"(a[2]), "r"(a[3]), "r"(b[0]), "r"(b[1]));
}
__device__ __forceinline__ void ldsm4(uint32_t* r, uint32_t saddr) {
    asm volatile("ldmatrix.sync.aligned.m8n8.x4.shared.b16 {%0,%1,%2,%3}, [%4];"
                 : "=r"(r[0]), "=r"(r[1]), "=r"(r[2]), "=r"(r[3]) : "r"(saddr));
}
__device__ __forceinline__ uint32_t smem_u32(const void* p) {
    uint32_t a;
    asm("{ .reg .u64 t; cvta.to.shared.u64 t, %1; cvt.u32.u64 %0, t; }" : "=r"(a) : "l"(p));
    return a;
}
__device__ __forceinline__ void mbar_init(uint32_t m, uint32_t cnt) {
    asm volatile("mbarrier.init.shared.b64 [%0], %1;" :: "r"(m), "r"(cnt) : "memory");
}
__device__ __forceinline__ void mbar_expect_tx(uint32_t m, uint32_t bytes) {
    asm volatile("mbarrier.arrive.expect_tx.shared.b64 _, [%0], %1;"
                 :: "r"(m), "r"(bytes) : "memory");
}
__device__ __forceinline__ void mbar_wait(uint32_t m, uint32_t parity) {
    asm volatile(
        "{ .reg .pred P;\n"
        "W_%=:\n"
        " mbarrier.try_wait.parity.acquire.cta.shared::cta.b64 P, [%0], %1, 0x989680;\n"
        " @P bra D_%=;\n"
        " bra W_%=;\n"
        "D_%=:\n}"
        :: "r"(m), "r"(parity) : "memory");
}
__device__ __forceinline__ void tma3(uint32_t smem, const CUtensorMap* m,
                                     int c0, int c1, int c2, uint32_t mbar) {
    asm volatile(
        "cp.async.bulk.tensor.3d.shared::cta.global.tile.mbarrier::complete_tx::bytes "
        "[%0], [%1, {%2, %3, %4}], [%5];"
        :: "r"(smem), "l"(m), "r"(c0), "r"(c1), "r"(c2), "r"(mbar) : "memory");
}
__device__ __forceinline__ void tma2(uint32_t smem, const CUtensorMap* m,
                                     int c0, int c1, uint32_t mbar) {
    asm volatile(
        "cp.async.bulk.tensor.2d.shared::cta.global.tile.mbarrier::complete_tx::bytes "
        "[%0], [%1, {%2, %3}], [%4];"
        :: "r"(smem), "l"(m), "r"(c0), "r"(c1), "r"(mbar) : "memory");
}

// ---------------- gemm kernel ----------------
__global__ __launch_bounds__(THREADS, 4)
void gemm_kernel(const __grid_constant__ CUtensorMap mapA,
                 const __grid_constant__ CUtensorMap mapW,
                 const int* __restrict__ mask32,
                 const float* __restrict__ bias,
                 float* __restrict__ out) {
    // A double-buffered (2 x 16 KB), W single-buffered (8 KB) = 40 KB.
    __shared__ alignas(1024) uint32_t sA[2][BM * 32];
    __shared__ alignas(1024) uint32_t sW[W_OUT * 32];
    __shared__ alignas(8) uint64_t s_mbarA[2];
    __shared__ alignas(8) uint64_t s_mbarW;

    const int h  = blockIdx.y;
    const int b0 = blockIdx.x * BM;
    const int t    = threadIdx.x;
    const int wid  = t >> 5;
    const int lane = t & 31;
    const int g  = lane >> 2;
    const int tq = lane & 3;
    const int wm = wid & 1;       // m offset wm*32 (plus +64 sub-tile)
    const int wn = wid >> 1;      // n offset wn*32

    const bool m64flag = mask_is_i64(mask32);
    int xrows[KSEL];
#pragma unroll
    for (int k = 0; k < KSEL; ++k) xrows[k] = mask_val(mask32, m64flag, h * KSEL + k);

    const uint32_t a0   = smem_u32(sA[0]);
    const uint32_t wB   = smem_u32(sW);
    uint32_t mbA[2] = {smem_u32(&s_mbarA[0]), smem_u32(&s_mbarA[1])};
    const uint32_t mbW  = smem_u32(&s_mbarW);

    if (t == 0) {
        mbar_init(mbA[0], 1);
        mbar_init(mbA[1], 1);
        mbar_init(mbW, 1);
    }
    __syncthreads();

    // prologue: chunk 0
    if (t == 0) {
        mbar_expect_tx(mbA[0], 16384);
        tma3(a0, &mapA, 0, xrows[0], b0, mbA[0]);
        mbar_expect_tx(mbW, 8192);
        tma2(wB, &mapW, 0, h * W_OUT, mbW);
    }

    // ldmatrix lane geometry (row offsets are multiples of 8 -> swizzle XOR
    // term is the constant lane&7).
    const int rx   = lane & 7;
    const int a_hi = lane >> 4;
    const int b_hi = (lane >> 3) & 1;
    uint32_t aRow[4], bRow[2];
#pragma unroll
    for (int amf = 0; amf < 4; ++amf) {
        int rowbase = wm * 32 + (amf >> 1) * 64 + (amf & 1) * 16;
        aRow[amf] = (uint32_t)((rowbase + (lane & 15)) * 128);
    }
#pragma unroll
    for (int pr = 0; pr < 2; ++pr)
        bRow[pr] = (uint32_t)((wn * 32 + pr * 16 + (lane & 7) + ((lane >> 4) << 3)) * 128);

    float acc[4][4][4];
#pragma unroll
    for (int a = 0; a < 4; ++a)
#pragma unroll
        for (int b = 0; b < 4; ++b)
#pragma unroll
            for (int c = 0; c < 4; ++c) acc[a][b][c] = 0.0f;

#pragma unroll
    for (int kc = 0; kc < KSEL; ++kc) {
        const int buf = kc & 1;

        // prefetch A for kc+1 (other buffer, freed by the sync ending kc-1)
        if (t == 0 && kc + 1 < KSEL) {
            const int nb = buf ^ 1;
            mbar_expect_tx(mbA[nb], 16384);
            tma3(a0 + nb * 16384, &mapA, 0, xrows[kc + 1], b0, mbA[nb]);
        }

        mbar_wait(mbA[buf], (kc >> 1) & 1);
        mbar_wait(mbW, kc & 1);

        const uint32_t aBase = a0 + buf * 16384;

        // ---- 4 k16-steps: 6 ldmatrix.x4 + 16 mma each (B shared by 2 m-subtiles) ----
#pragma unroll
        for (int ks = 0; ks < 4; ++ks) {
            uint32_t ah[16], bh[8];
            const int ks2 = ks * 2;
            const uint32_t akOff = (uint32_t)(((ks2 + a_hi) ^ rx) << 4);
            const uint32_t bkOff = (uint32_t)(((ks2 + b_hi) ^ rx) << 4);
#pragma unroll
            for (int pr = 0; pr < 2; ++pr)
                ldsm4(&bh[pr * 4], wB + bRow[pr] + bkOff);
#pragma unroll
            for (int amf = 0; amf < 4; ++amf)
                ldsm4(&ah[amf * 4], aBase + aRow[amf] + akOff);
#pragma unroll
            for (int amf = 0; amf < 4; ++amf)
#pragma unroll
                for (int nf = 0; nf < 4; ++nf)
                    mma16816(acc[amf][nf], &ah[amf * 4], &bh[nf * 2]);
        }
        __syncthreads();   // A buffer free for kc+2; W buffer free for kc+1

        if (t == 0 && kc + 1 < KSEL) {
            mbar_expect_tx(mbW, 8192);
            tma2(wB, &mapW, (kc + 1) * 64, h * W_OUT, mbW);
        }
    }

    // ---- epilogue: add bias, float2 stores ----
#pragma unroll
    for (int nf = 0; nf < 4; ++nf) {
        int col = wn * 32 + nf * 8 + tq * 2;
        float bx = bias[h * W_OUT + col];
        float by = bias[h * W_OUT + col + 1];
#pragma unroll
        for (int amf = 0; amf < 4; ++amf) {
            int row0 = b0 + wm * 32 + (amf >> 1) * 64 + (amf & 1) * 16 + g;
            float2 v0 = {acc[amf][nf][0] + bx, acc[amf][nf][1] + by};
            float2 v1 = {acc[amf][nf][2] + bx, acc[amf][nf][3] + by};
            *reinterpret_cast<float2*>(
                out + ((size_t)row0 * H_OUT + h) * W_OUT + col) = v0;
            *reinterpret_cast<float2*>(
                out + ((size_t)(row0 + 8) * H_OUT + h) * W_OUT + col) = v1;
        }
    }
}

} // namespace asl

// ---------------- host ----------------
typedef CUresult (*EncodeTiledFn)(
    CUtensorMap*, CUtensorMapDataType, cuuint32_t, void*,
    const cuuint64_t*, const cuuint64_t*, const cuuint32_t*, const cuuint32_t*,
    CUtensorMapInterleave, CUtensorMapSwizzle, CUtensorMapL2promotion,
    CUtensorMapFloatOOBfill);

extern "C" void kernel_launch(void* const* d_in, const int* in_sizes, int n_in,
                              void* d_out, int out_size) {
    const float* x      = (const float*)d_in[0];
    const int*   mask32 = (const int*)d_in[1];
    const float* W      = (const float*)d_in[2];
    const float* bias   = (const float*)d_in[3];
    float*       out    = (float*)d_out;

    asl::split_kernel<<<2048, 256>>>(
        reinterpret_cast<const float4*>(x), reinterpret_cast<const float4*>(W));

    void* xhi = nullptr; void* whi = nullptr;
    cudaGetSymbolAddress(&xhi, asl::g_xhi);
    cudaGetSymbolAddress(&whi, asl::g_whi);

    EncodeTiledFn enc = nullptr;
    cudaDriverEntryPointQueryResult qres;
    cudaGetDriverEntryPoint("cuTensorMapEncodeTiled", (void**)&enc,
                            cudaEnableDefault, &qres);

    CUtensorMap mA{}, mW{};
    {
        cuuint64_t dims[3]    = {64, 128, 512};
        cuuint64_t strides[2] = {128, 128ull * 128};
        cuuint32_t box[3]     = {64, 1, 128};      // 128 batch rows per load
        cuuint32_t es[3]      = {1, 1, 1};
        enc(&mA, CU_TENSOR_MAP_DATA_TYPE_FLOAT16, 3, xhi, dims, strides, box, es,
            CU_TENSOR_MAP_INTERLEAVE_NONE, CU_TENSOR_MAP_SWIZZLE_128B,
            CU_TENSOR_MAP_L2_PROMOTION_L2_128B, CU_TENSOR_MAP_FLOAT_OOB_FILL_NONE);
    }
    {
        cuuint64_t dims[2]    = {256, 256ull * 64};
        cuuint64_t strides[1] = {512};
        cuuint32_t box[2]     = {64, 64};
        cuuint32_t es[2]      = {1, 1};
        enc(&mW, CU_TENSOR_MAP_DATA_TYPE_FLOAT16, 2, whi, dims, strides, box, es,
            CU_TENSOR_MAP_INTERLEAVE_NONE, CU_TENSOR_MAP_SWIZZLE_128B,
            CU_TENSOR_MAP_L2_PROMOTION_L2_128B, CU_TENSOR_MAP_FLOAT_OOB_FILL_NONE);
    }

    dim3 grid(asl::B_SZ / asl::BM, asl::H_OUT);   // (4, 256)
    asl::gemm_kernel<<<grid, asl::THREADS>>>(mA, mW, mask32, bias, out);
}